// round 1
// baseline (speedup 1.0000x reference)
#include <cuda_runtime.h>
#include <math.h>

#define B_  32
#define G_  50
#define NC_ 80
#define NA_ 8400

// ---------------- device scratch (no cudaMalloc allowed) ----------------
__device__ float4        g_box [B_*NA_];       // decoded cx,cy,w,h
__device__ float         g_obj [B_*NA_];       // obj logit
__device__ float         g_Bo  [B_*NA_];       // 1 + exp(-obj)
__device__ float         g_s   [B_*NA_];       // sum_c log1p(-p_c)
__device__ unsigned char g_fg  [B_*NA_];       // anchor is candidate for any gt
__device__ float         g_cost[B_*G_*NA_];    // 53.8 MB
__device__ float         g_ioum[B_*G_*NA_];    // 53.8 MB (cand-masked iou)
__device__ float         g_gtbox[B_*G_*4];
__device__ int           g_gtcls[B_*G_];
__device__ unsigned char g_gtval[B_*G_];
__device__ float         g_thr [B_*G_];
__device__ double        g_accb[B_][4];        // iou, obj, cls, numfg partial sums

__device__ __forceinline__ void anchor_map(int a, int& hw, int& W, int& HW, float& st) {
    if (a < 6400)      { hw = a;        W = 80; HW = 6400; st = 8.f;  }
    else if (a < 8000) { hw = a - 6400; W = 40; HW = 1600; st = 16.f; }
    else               { hw = a - 8000; W = 20; HW = 400;  st = 32.f; }
}

__device__ __forceinline__ float bce_logit(float x, float y) {
    return fmaxf(x, 0.f) - x * y + log1pf(expf(-fabsf(x)));
}

// ---------------- K0: zero accumulators ----------------
__global__ void k_zero() {
    int i = threadIdx.x;
    if (i < B_ * 4) ((double*)g_accb)[i] = 0.0;
}

// ---------------- K1: decode + per-anchor stats ----------------
__global__ void k_decode(const float* __restrict__ out0,
                         const float* __restrict__ out1,
                         const float* __restrict__ out2) {
    int idx = blockIdx.x * blockDim.x + threadIdx.x;
    if (idx >= B_ * NA_) return;
    int b = idx / NA_, a = idx - b * NA_;
    int hw, W, HW; float st;
    anchor_map(a, hw, W, HW, st);
    const float* src = (a < 6400) ? out0 : (a < 8000) ? out1 : out2;
    const float* p = src + (size_t)b * 85 * HW + hw;

    float tx = p[0], ty = p[HW], tw = p[2*HW], th = p[3*HW], to = p[4*HW];
    int h = hw / W, w = hw - h * W;
    g_box[idx] = make_float4((tx + (float)w) * st, (ty + (float)h) * st,
                             expf(tw) * st, expf(th) * st);
    g_obj[idx] = to;
    float Bo = 1.f + expf(-to);
    g_Bo[idx] = Bo;

    float s = 0.f;
    #pragma unroll 4
    for (int c = 0; c < NC_; c++) {
        float xc = p[(5 + c) * HW];
        float A  = 1.f + expf(-xc);
        float pv = rsqrtf(A * Bo);                 // sqrt(sig(x)*sig(o))
        pv = fminf(fmaxf(pv, 1e-7f), 1.f - 1e-6f);
        s += log1pf(-pv);
    }
    g_s[idx] = s;
}

// ---------------- K2: gt extraction ----------------
__global__ void k_gt(const float* __restrict__ labels) {
    int i = blockIdx.x * blockDim.x + threadIdx.x;
    if (i >= B_ * G_) return;
    const float* l = labels + i * 5;
    float c = l[0], x = l[1], y = l[2], w = l[3], h = l[4];
    g_gtval[i] = (c + x + y + w + h) > 0.f;
    g_gtbox[i*4+0] = x; g_gtbox[i*4+1] = y; g_gtbox[i*4+2] = w; g_gtbox[i*4+3] = h;
    g_gtcls[i] = (int)c;
}

// ---------------- K3: fg mask per anchor ----------------
__global__ void k_fg() {
    __shared__ float sgt[G_*4];
    __shared__ unsigned char sval[G_];
    int b = blockIdx.y;
    if (threadIdx.x < G_*4) sgt[threadIdx.x] = g_gtbox[b*G_*4 + threadIdx.x];
    if (threadIdx.x < G_)   sval[threadIdx.x] = g_gtval[b*G_ + threadIdx.x];
    __syncthreads();
    int a = blockIdx.x * blockDim.x + threadIdx.x;
    if (a >= NA_) return;
    int hw, W, HW; float st;
    anchor_map(a, hw, W, HW, st);
    int h = hw / W, w = hw - h * W;
    float cx = ((float)w + 0.5f) * st, cy = ((float)h + 0.5f) * st;
    float rs = 2.5f * st;
    bool fg = false;
    for (int g = 0; g < G_; g++) {
        if (!sval[g]) continue;
        float gx = sgt[g*4], gy = sgt[g*4+1], gw = sgt[g*4+2], gh = sgt[g*4+3];
        bool ib = (cx > gx - 0.5f*gw) && (cx < gx + 0.5f*gw) &&
                  (cy > gy - 0.5f*gh) && (cy < gy + 0.5f*gh);
        bool ic = (fabsf(cx - gx) < rs) && (fabsf(cy - gy) < rs);
        fg |= (ib | ic);
    }
    g_fg[b*NA_ + a] = fg ? 1 : 0;
}

// ---------------- K4: cost + iou matrices ----------------
// Non-cand entries: cost=1e30 fill, iou_m=0. Provably equivalent to reference
// (cand costs < ~1.1e5 << 1e9; thr always drawn from cand entries since
// dyn_k <= #cand whenever #cand >= 1; argmin per fg column lies in cand rows).
__global__ void k_cost(const float* __restrict__ out0,
                       const float* __restrict__ out1,
                       const float* __restrict__ out2) {
    int b = blockIdx.z, g = blockIdx.y;
    int a = blockIdx.x * blockDim.x + threadIdx.x;
    if (a >= NA_) return;
    int gi = b * G_ + g;
    int row = gi * NA_;
    int idx = b * NA_ + a;
    bool cand = g_fg[idx] && g_gtval[gi];
    if (!cand) {
        g_cost[row + a] = 1e30f;
        g_ioum[row + a] = 0.f;
        return;
    }
    float gx = g_gtbox[gi*4+0], gy = g_gtbox[gi*4+1];
    float gw = g_gtbox[gi*4+2], gh = g_gtbox[gi*4+3];
    float4 bb = g_box[idx];
    // pairwise iou (reference formula, no clip, en gate)
    float tlx = fmaxf(gx - gw*0.5f, bb.x - bb.z*0.5f);
    float tly = fmaxf(gy - gh*0.5f, bb.y - bb.w*0.5f);
    float brx = fminf(gx + gw*0.5f, bb.x + bb.z*0.5f);
    float bry = fminf(gy + gh*0.5f, bb.y + bb.w*0.5f);
    float en  = (tlx < brx && tly < bry) ? 1.f : 0.f;
    float inter = (brx - tlx) * (bry - tly) * en;
    float iou = inter / (gw*gh + bb.z*bb.w - inter + 1e-12f);
    // geometry
    int hw, W, HW; float st;
    anchor_map(a, hw, W, HW, st);
    int h = hw / W, w = hw - h * W;
    float cx = ((float)w + 0.5f) * st, cy = ((float)h + 0.5f) * st;
    bool ib = (cx > gx - 0.5f*gw) && (cx < gx + 0.5f*gw) &&
              (cy > gy - 0.5f*gh) && (cy < gy + 0.5f*gh);
    float rs = 2.5f * st;
    bool ic = (fabsf(cx - gx) < rs) && (fabsf(cy - gy) < rs);
    bool geom = ib && ic;
    // cls cost for this gt's class
    const float* src = (a < 6400) ? out0 : (a < 8000) ? out1 : out2;
    int cg = g_gtcls[gi];
    float xc = src[((size_t)b * 85 + 5 + cg) * HW + hw];
    float A  = 1.f + expf(-xc);
    float pv = rsqrtf(A * g_Bo[idx]);
    pv = fminf(fmaxf(pv, 1e-7f), 1.f - 1e-6f);
    float lp = logf(pv);
    float l1 = log1pf(-pv);
    float cls_cost = -lp + l1 - g_s[idx];
    float cost = cls_cost + 3.f * (-logf(iou + 1e-8f)) + (geom ? 0.f : 100000.f);
    g_cost[row + a] = cost;
    g_ioum[row + a] = iou;
}

// ---------------- K5: per (b,g) row: dyn_k and threshold ----------------
__global__ void k_topk() {
    int gwarp = (blockIdx.x * blockDim.x + threadIdx.x) >> 5;
    int lane = threadIdx.x & 31;
    if (gwarp >= B_ * G_) return;
    const float* crow = g_cost + (size_t)gwarp * NA_;
    const float* irow = g_ioum + (size_t)gwarp * NA_;

    float lc[10], li[10];
    #pragma unroll
    for (int i = 0; i < 10; i++) { lc[i] = 3.0e38f; li[i] = -1.f; }

    for (int a = lane; a < NA_; a += 32) {
        float c = crow[a];
        if (c < lc[9]) {
            int j = 9;
            while (j > 0 && lc[j-1] > c) { lc[j] = lc[j-1]; j--; }
            lc[j] = c;
        }
        float v = irow[a];
        if (v > li[9]) {
            int j = 9;
            while (j > 0 && li[j-1] < v) { li[j] = li[j-1]; j--; }
            li[j] = v;
        }
    }

    // merge iou top-10 (descending), sum in descending order -> dyn_k
    float isum = 0.f;
    {
        int ptr = 0; float head = li[0];
        for (int k = 0; k < 10; k++) {
            float bv = head; int bl = lane;
            #pragma unroll
            for (int off = 16; off; off >>= 1) {
                float ov = __shfl_down_sync(0xffffffffu, bv, off);
                int   ol = __shfl_down_sync(0xffffffffu, bl, off);
                if (ov > bv || (ov == bv && ol < bl)) { bv = ov; bl = ol; }
            }
            bv = __shfl_sync(0xffffffffu, bv, 0);
            bl = __shfl_sync(0xffffffffu, bl, 0);
            if (lane == bl) { ptr++; head = (ptr < 10) ? li[ptr] : -3.0e38f; }
            isum += bv;
        }
    }
    int dynk = (int)isum;
    if (dynk < 1) dynk = 1;
    if (dynk > 10) dynk = 10;

    // merge cost smallest-10 (ascending), pick (dynk-1)-th
    float thr = 0.f;
    {
        int ptr = 0; float head = lc[0];
        for (int k = 0; k < 10; k++) {
            float bv = head; int bl = lane;
            #pragma unroll
            for (int off = 16; off; off >>= 1) {
                float ov = __shfl_down_sync(0xffffffffu, bv, off);
                int   ol = __shfl_down_sync(0xffffffffu, bl, off);
                if (ov < bv || (ov == bv && ol < bl)) { bv = ov; bl = ol; }
            }
            bv = __shfl_sync(0xffffffffu, bv, 0);
            bl = __shfl_sync(0xffffffffu, bl, 0);
            if (lane == bl) { ptr++; head = (ptr < 10) ? lc[ptr] : 3.0e38f; }
            if (k == dynk - 1) thr = bv;
        }
    }
    if (lane == 0) g_thr[gwarp] = thr;
}

// ---------------- K6: resolve matches + per-anchor losses ----------------
__global__ void k_resolve(const float* __restrict__ out0,
                          const float* __restrict__ out1,
                          const float* __restrict__ out2) {
    __shared__ float sthr[G_];
    __shared__ unsigned char sval[G_];
    int b = blockIdx.y;
    if (threadIdx.x < G_) {
        sthr[threadIdx.x] = g_thr[b*G_ + threadIdx.x];
        sval[threadIdx.x] = g_gtval[b*G_ + threadIdx.x];
    }
    __syncthreads();

    int a = blockIdx.x * blockDim.x + threadIdx.x;
    float liou = 0.f, lobj = 0.f, lcls = 0.f, lfg = 0.f;
    if (a < NA_) {
        int idx = b * NA_ + a;
        bool fgA = g_fg[idx];
        unsigned long long mask = 0ull;
        int count = 0, bestg = 0;
        float minc = 3.4e38f;
        for (int g = 0; g < G_; g++) {
            float c = __ldg(&g_cost[(b*G_ + g) * NA_ + a]);
            if (c < minc) { minc = c; bestg = g; }
            if (fgA && sval[g] && (c <= sthr[g])) { mask |= 1ull << g; count++; }
        }
        if (count > 1) mask &= (1ull << bestg);
        bool fgfin = (mask != 0ull);
        int mg = fgfin ? (__ffsll((long long)mask) - 1) : 0;
        float piou = 0.f;
        unsigned long long mm = mask;
        while (mm) {
            int g = __ffsll((long long)mm) - 1;
            mm &= mm - 1;
            piou += g_ioum[(b*G_ + g) * NA_ + a];
        }

        float obj = g_obj[idx];
        float y = fgfin ? 1.f : 0.f;
        lobj = bce_logit(obj, y);
        lfg = y;

        if (fgfin) {
            float4 bb = g_box[idx];
            int gi = b * G_ + mg;
            float gx = g_gtbox[gi*4+0], gy = g_gtbox[gi*4+1];
            float gw = g_gtbox[gi*4+2], gh = g_gtbox[gi*4+3];
            // iou loss (clip + en)
            float tlx = fmaxf(bb.x - bb.z*0.5f, gx - gw*0.5f);
            float tly = fmaxf(bb.y - bb.w*0.5f, gy - gh*0.5f);
            float brx = fminf(bb.x + bb.z*0.5f, gx + gw*0.5f);
            float bry = fminf(bb.y + bb.w*0.5f, gy + gh*0.5f);
            float en  = (tlx < brx && tly < bry) ? 1.f : 0.f;
            float inter = fmaxf(brx - tlx, 0.f) * fmaxf(bry - tly, 0.f) * en;
            float uni = bb.z*bb.w + gw*gh - inter + 1e-16f;
            float iou = inter / uni;
            liou = 1.f - iou * iou;
            // cls loss over 80 classes
            int mcls = g_gtcls[gi];
            int hw, W, HW; float st;
            anchor_map(a, hw, W, HW, st);
            const float* src = (a < 6400) ? out0 : (a < 8000) ? out1 : out2;
            const float* p = src + (size_t)b * 85 * HW + hw;
            #pragma unroll 4
            for (int c = 0; c < NC_; c++) {
                float x = p[(5 + c) * HW];
                float t = (c == mcls) ? piou : 0.f;
                lcls += bce_logit(x, t);
            }
        }
    }

    // block reduce 4 floats -> per-batch double accumulators
    #pragma unroll
    for (int off = 16; off; off >>= 1) {
        liou += __shfl_down_sync(0xffffffffu, liou, off);
        lobj += __shfl_down_sync(0xffffffffu, lobj, off);
        lcls += __shfl_down_sync(0xffffffffu, lcls, off);
        lfg  += __shfl_down_sync(0xffffffffu, lfg,  off);
    }
    __shared__ float s4[8][4];
    int wid = threadIdx.x >> 5, lane = threadIdx.x & 31;
    if (lane == 0) { s4[wid][0] = liou; s4[wid][1] = lobj; s4[wid][2] = lcls; s4[wid][3] = lfg; }
    __syncthreads();
    if (threadIdx.x == 0) {
        float a0 = 0.f, a1 = 0.f, a2 = 0.f, a3 = 0.f;
        for (int i = 0; i < 8; i++) { a0 += s4[i][0]; a1 += s4[i][1]; a2 += s4[i][2]; a3 += s4[i][3]; }
        atomicAdd(&g_accb[b][0], (double)a0);
        atomicAdd(&g_accb[b][1], (double)a1);
        atomicAdd(&g_accb[b][2], (double)a2);
        atomicAdd(&g_accb[b][3], (double)a3);
    }
}

// ---------------- K7: finalize ----------------
__global__ void k_final(float* __restrict__ out) {
    if (threadIdx.x == 0) {
        double si = 0.0, so = 0.0, sc = 0.0, nf = 0.0;
        for (int b = 0; b < B_; b++) {
            si += g_accb[b][0]; so += g_accb[b][1];
            sc += g_accb[b][2]; nf += g_accb[b][3];
        }
        if (nf < 1.0) nf = 1.0;
        out[0] = (float)((5.0 * si + so + sc) / nf);
    }
}

// ---------------- launch ----------------
extern "C" void kernel_launch(void* const* d_in, const int* in_sizes, int n_in,
                              void* d_out, int out_size) {
    const float* out0   = (const float*)d_in[0];
    const float* out1   = (const float*)d_in[1];
    const float* out2   = (const float*)d_in[2];
    const float* labels = (const float*)d_in[3];
    float* out = (float*)d_out;

    k_zero<<<1, 128>>>();
    k_decode<<<(B_*NA_ + 255) / 256, 256>>>(out0, out1, out2);
    k_gt<<<(B_*G_ + 127) / 128, 128>>>(labels);
    {
        dim3 g((NA_ + 255) / 256, B_);
        k_fg<<<g, 256>>>();
    }
    {
        dim3 g((NA_ + 255) / 256, G_, B_);
        k_cost<<<g, 256>>>(out0, out1, out2);
    }
    k_topk<<<(B_*G_*32 + 127) / 128, 128>>>();
    {
        dim3 g((NA_ + 255) / 256, B_);
        k_resolve<<<g, 256>>>(out0, out1, out2);
    }
    k_final<<<1, 32>>>(out);
}

// round 2
// speedup vs baseline: 2.4080x; 2.4080x over previous
#include <cuda_runtime.h>
#include <math.h>

#define B_  32
#define G_  50
#define NC_ 80
#define NA_ 8400

// ---------------- device scratch ----------------
__device__ float4        g_box [B_*NA_];       // decoded cx,cy,w,h (all anchors)
__device__ float         g_obj [B_*NA_];
__device__ float         g_Bo  [B_*NA_];       // 1 + exp(-obj)
__device__ float         g_s   [B_*NA_];       // sum_c log1p(-p_c)  (fg anchors only)
__device__ unsigned char g_fg  [B_*NA_];
__device__ int           g_flist[B_*NA_];      // compacted fg anchor ids (ascending)
__device__ int           g_nfg [B_];
__device__ float         g_cost[B_*G_*NA_];    // [b][g][f] f = compact index
__device__ float         g_ioum[B_*G_*NA_];
__device__ float         g_gtbox[B_*G_*4];
__device__ int           g_gtcls[B_*G_];
__device__ unsigned char g_gtval[B_*G_];
__device__ float         g_thr [B_*G_];
__device__ double        g_accb[B_][4];        // iou, obj, cls, numfg

__device__ __forceinline__ void anchor_map(int a, int& hw, int& W, int& HW, float& st) {
    if (a < 6400)      { hw = a;        W = 80; HW = 6400; st = 8.f;  }
    else if (a < 8000) { hw = a - 6400; W = 40; HW = 1600; st = 16.f; }
    else               { hw = a - 8000; W = 20; HW = 400;  st = 32.f; }
}

__device__ __forceinline__ float bce_logit(float x, float y) {
    return fmaxf(x, 0.f) - x * y + log1pf(expf(-fabsf(x)));
}

// ---------------- K1: gt extraction + zero accumulators ----------------
__global__ void k_gt(const float* __restrict__ labels) {
    int i = blockIdx.x * blockDim.x + threadIdx.x;
    if (i < B_ * 4) ((double*)g_accb)[i] = 0.0;
    if (i < B_) g_nfg[i] = 0;
    if (i >= B_ * G_) return;
    const float* l = labels + i * 5;
    float c = l[0], x = l[1], y = l[2], w = l[3], h = l[4];
    g_gtval[i] = (c + x + y + w + h) > 0.f;
    g_gtbox[i*4+0] = x; g_gtbox[i*4+1] = y; g_gtbox[i*4+2] = w; g_gtbox[i*4+3] = h;
    g_gtcls[i] = (int)c;
}

// ---------------- K2: decode + fg + obj-softplus + s (fg only) ----------------
__global__ void k_decode(const float* __restrict__ out0,
                         const float* __restrict__ out1,
                         const float* __restrict__ out2) {
    __shared__ float sgt[G_*4];
    __shared__ unsigned char sval[G_];
    int b = blockIdx.y;
    if (threadIdx.x < G_*4) sgt[threadIdx.x] = g_gtbox[b*G_*4 + threadIdx.x];
    if (threadIdx.x < G_)   sval[threadIdx.x] = g_gtval[b*G_ + threadIdx.x];
    __syncthreads();

    int a = blockIdx.x * blockDim.x + threadIdx.x;
    float softplus_obj = 0.f;
    if (a < NA_) {
        int idx = b * NA_ + a;
        int hw, W, HW; float st;
        anchor_map(a, hw, W, HW, st);
        const float* src = (a < 6400) ? out0 : (a < 8000) ? out1 : out2;
        const float* p = src + (size_t)b * 85 * HW + hw;

        float tx = p[0], ty = p[HW], tw = p[2*HW], th = p[3*HW], to = p[4*HW];
        int h = hw / W, w = hw - h * W;
        g_box[idx] = make_float4((tx + (float)w) * st, (ty + (float)h) * st,
                                 expf(tw) * st, expf(th) * st);
        g_obj[idx] = to;
        float Bo = 1.f + expf(-to);
        g_Bo[idx] = Bo;
        softplus_obj = fmaxf(to, 0.f) + log1pf(expf(-fabsf(to)));

        // fg test
        float cx = ((float)w + 0.5f) * st, cy = ((float)h + 0.5f) * st;
        float rs = 2.5f * st;
        bool fg = false;
        for (int g = 0; g < G_; g++) {
            if (!sval[g]) continue;
            float gx = sgt[g*4], gy = sgt[g*4+1], gw = sgt[g*4+2], gh = sgt[g*4+3];
            bool ib = (cx > gx - 0.5f*gw) && (cx < gx + 0.5f*gw) &&
                      (cy > gy - 0.5f*gh) && (cy < gy + 0.5f*gh);
            bool ic = (fabsf(cx - gx) < rs) && (fabsf(cy - gy) < rs);
            fg |= (ib | ic);
        }
        g_fg[idx] = fg ? 1 : 0;

        if (fg) {
            float s0 = 0.f, s1 = 0.f;
            #pragma unroll 4
            for (int c = 0; c < NC_; c += 2) {
                float xc0 = p[(5 + c) * HW];
                float xc1 = p[(6 + c) * HW];
                float pv0 = rsqrtf((1.f + expf(-xc0)) * Bo);
                float pv1 = rsqrtf((1.f + expf(-xc1)) * Bo);
                pv0 = fminf(fmaxf(pv0, 1e-7f), 1.f - 1e-6f);
                pv1 = fminf(fmaxf(pv1, 1e-7f), 1.f - 1e-6f);
                s0 += log1pf(-pv0);
                s1 += log1pf(-pv1);
            }
            g_s[idx] = s0 + s1;
        }
    }

    // block-reduce softplus_obj -> accb[b][1]
    #pragma unroll
    for (int off = 16; off; off >>= 1)
        softplus_obj += __shfl_down_sync(0xffffffffu, softplus_obj, off);
    __shared__ float swsum[8];
    int wid = threadIdx.x >> 5, lane = threadIdx.x & 31;
    if (lane == 0) swsum[wid] = softplus_obj;
    __syncthreads();
    if (threadIdx.x == 0) {
        float t = 0.f;
        for (int i = 0; i < 8; i++) t += swsum[i];
        atomicAdd(&g_accb[b][1], (double)t);
    }
}

// ---------------- K3: ordered compaction (block per batch) ----------------
__global__ void k_compact() {
    int b = blockIdx.x;
    __shared__ int s_base;
    __shared__ int warpsum[8];
    if (threadIdx.x == 0) s_base = 0;
    __syncthreads();
    int lane = threadIdx.x & 31, wid = threadIdx.x >> 5;
    for (int start = 0; start < NA_; start += 256) {
        int a = start + threadIdx.x;
        int flag = (a < NA_) ? (int)g_fg[b*NA_ + a] : 0;
        unsigned bal = __ballot_sync(0xffffffffu, flag);
        int pre = __popc(bal & ((1u << lane) - 1));
        if (lane == 0) warpsum[wid] = __popc(bal);
        __syncthreads();
        int woff = 0, tot = 0;
        #pragma unroll
        for (int i = 0; i < 8; i++) { if (i < wid) woff += warpsum[i]; tot += warpsum[i]; }
        if (flag) g_flist[b*NA_ + s_base + woff + pre] = a;
        __syncthreads();
        if (threadIdx.x == 0) s_base += tot;
        __syncthreads();
    }
    if (threadIdx.x == 0) g_nfg[b] = s_base;
}

// ---------------- K4: compact cost/iou, g-loop inside ----------------
__global__ void k_cost(const float* __restrict__ out0,
                       const float* __restrict__ out1,
                       const float* __restrict__ out2) {
    __shared__ float sgt[G_*4];
    __shared__ unsigned char sval[G_];
    __shared__ int scls[G_];
    int b = blockIdx.y;
    if (threadIdx.x < G_*4) sgt[threadIdx.x] = g_gtbox[b*G_*4 + threadIdx.x];
    if (threadIdx.x < G_) {
        sval[threadIdx.x] = g_gtval[b*G_ + threadIdx.x];
        scls[threadIdx.x] = g_gtcls[b*G_ + threadIdx.x];
    }
    __syncthreads();

    int f = blockIdx.x * blockDim.x + threadIdx.x;
    if (f >= g_nfg[b]) return;
    int a = g_flist[b*NA_ + f];
    int idx = b * NA_ + a;
    float4 bb = g_box[idx];
    float Bo = g_Bo[idx];
    float s  = g_s[idx];
    int hw, W, HW; float st;
    anchor_map(a, hw, W, HW, st);
    int h = hw / W, w = hw - h * W;
    float cx = ((float)w + 0.5f) * st, cy = ((float)h + 0.5f) * st;
    float rs = 2.5f * st;
    const float* src = (a < 6400) ? out0 : (a < 8000) ? out1 : out2;
    const float* p = src + (size_t)b * 85 * HW + hw;

    float bz2 = bb.z * 0.5f, bw2 = bb.w * 0.5f;
    float areab = bb.z * bb.w;

    for (int g = 0; g < G_; g++) {
        if (!sval[g]) continue;
        float gx = sgt[g*4], gy = sgt[g*4+1], gw = sgt[g*4+2], gh = sgt[g*4+3];
        float tlx = fmaxf(gx - gw*0.5f, bb.x - bz2);
        float tly = fmaxf(gy - gh*0.5f, bb.y - bw2);
        float brx = fminf(gx + gw*0.5f, bb.x + bz2);
        float bry = fminf(gy + gh*0.5f, bb.y + bw2);
        float en  = (tlx < brx && tly < bry) ? 1.f : 0.f;
        float inter = (brx - tlx) * (bry - tly) * en;
        float iou = inter / (gw*gh + areab - inter + 1e-12f);

        bool ib = (cx > gx - 0.5f*gw) && (cx < gx + 0.5f*gw) &&
                  (cy > gy - 0.5f*gh) && (cy < gy + 0.5f*gh);
        bool ic = (fabsf(cx - gx) < rs) && (fabsf(cy - gy) < rs);
        bool geom = ib && ic;

        float xc = __ldg(&p[(5 + scls[g]) * HW]);
        float pv = rsqrtf((1.f + expf(-xc)) * Bo);
        pv = fminf(fmaxf(pv, 1e-7f), 1.f - 1e-6f);
        float cls_cost = -logf(pv) + log1pf(-pv) - s;
        float cost = cls_cost - 3.f * logf(iou + 1e-8f) + (geom ? 0.f : 100000.f);

        int row = (b * G_ + g) * NA_;
        g_cost[row + f] = cost;
        g_ioum[row + f] = iou;
    }
}

// ---------------- K5: per (b,g): dyn_k and threshold ----------------
__global__ void k_topk() {
    int gwarp = (blockIdx.x * blockDim.x + threadIdx.x) >> 5;
    int lane = threadIdx.x & 31;
    if (gwarp >= B_ * G_) return;
    int b = gwarp / G_, g = gwarp - b * G_;
    if (!g_gtval[gwarp]) return;
    int N = g_nfg[b];
    if (N == 0) return;
    const float* crow = g_cost + (size_t)gwarp * NA_;
    const float* irow = g_ioum + (size_t)gwarp * NA_;

    float lc[10], li[10];
    #pragma unroll
    for (int i = 0; i < 10; i++) { lc[i] = 3.0e38f; li[i] = 0.f; }

    for (int a = lane; a < N; a += 32) {
        float c = crow[a];
        if (c < lc[9]) {
            int j = 9;
            while (j > 0 && lc[j-1] > c) { lc[j] = lc[j-1]; j--; }
            lc[j] = c;
        }
        float v = irow[a];
        if (v > li[9]) {
            int j = 9;
            while (j > 0 && li[j-1] < v) { li[j] = li[j-1]; j--; }
            li[j] = v;
        }
    }

    float isum = 0.f;
    {
        int ptr = 0; float head = li[0];
        for (int k = 0; k < 10; k++) {
            float bv = head; int bl = lane;
            #pragma unroll
            for (int off = 16; off; off >>= 1) {
                float ov = __shfl_down_sync(0xffffffffu, bv, off);
                int   ol = __shfl_down_sync(0xffffffffu, bl, off);
                if (ov > bv || (ov == bv && ol < bl)) { bv = ov; bl = ol; }
            }
            bv = __shfl_sync(0xffffffffu, bv, 0);
            bl = __shfl_sync(0xffffffffu, bl, 0);
            if (lane == bl) { ptr++; head = (ptr < 10) ? li[ptr] : -3.0e38f; }
            isum += bv;
        }
    }
    int dynk = (int)isum;
    if (dynk < 1) dynk = 1;
    if (dynk > 10) dynk = 10;
    if (dynk > N) dynk = N;

    float thr = 0.f;
    {
        int ptr = 0; float head = lc[0];
        for (int k = 0; k < 10; k++) {
            float bv = head; int bl = lane;
            #pragma unroll
            for (int off = 16; off; off >>= 1) {
                float ov = __shfl_down_sync(0xffffffffu, bv, off);
                int   ol = __shfl_down_sync(0xffffffffu, bl, off);
                if (ov < bv || (ov == bv && ol < bl)) { bv = ov; bl = ol; }
            }
            bv = __shfl_sync(0xffffffffu, bv, 0);
            bl = __shfl_sync(0xffffffffu, bl, 0);
            if (lane == bl) { ptr++; head = (ptr < 10) ? lc[ptr] : 3.0e38f; }
            if (k == dynk - 1) thr = bv;
        }
    }
    if (lane == 0) g_thr[gwarp] = thr;
}

// ---------------- K6: resolve + losses (compact anchors only) ----------------
__global__ void k_resolve(const float* __restrict__ out0,
                          const float* __restrict__ out1,
                          const float* __restrict__ out2) {
    __shared__ float sthr[G_];
    __shared__ unsigned char sval[G_];
    int b = blockIdx.y;
    if (threadIdx.x < G_) {
        sthr[threadIdx.x] = g_thr[b*G_ + threadIdx.x];
        sval[threadIdx.x] = g_gtval[b*G_ + threadIdx.x];
    }
    __syncthreads();

    int f = blockIdx.x * blockDim.x + threadIdx.x;
    float liou = 0.f, lobj = 0.f, lcls = 0.f, lfg = 0.f;
    if (f < g_nfg[b]) {
        int a = g_flist[b*NA_ + f];
        int idx = b * NA_ + a;
        unsigned long long mask = 0ull;
        int count = 0, bestg = 0;
        float minc = 3.4e38f;
        for (int g = 0; g < G_; g++) {
            if (!sval[g]) continue;
            float c = __ldg(&g_cost[(b*G_ + g) * NA_ + f]);
            if (c < minc) { minc = c; bestg = g; }
            if (c <= sthr[g]) { mask |= 1ull << g; count++; }
        }
        if (count > 1) mask &= (1ull << bestg);
        bool fgfin = (mask != 0ull);
        if (fgfin) {
            int mg = __ffsll((long long)mask) - 1;
            float piou = 0.f;
            unsigned long long mm = mask;
            while (mm) {
                int g = __ffsll((long long)mm) - 1;
                mm &= mm - 1;
                piou += g_ioum[(b*G_ + g) * NA_ + f];
            }
            lfg = 1.f;
            lobj = -g_obj[idx];   // bce(x,1)-bce(x,0); softplus part already accumulated

            float4 bb = g_box[idx];
            int gi = b * G_ + mg;
            float gx = g_gtbox[gi*4+0], gy = g_gtbox[gi*4+1];
            float gw = g_gtbox[gi*4+2], gh = g_gtbox[gi*4+3];
            float tlx = fmaxf(bb.x - bb.z*0.5f, gx - gw*0.5f);
            float tly = fmaxf(bb.y - bb.w*0.5f, gy - gh*0.5f);
            float brx = fminf(bb.x + bb.z*0.5f, gx + gw*0.5f);
            float bry = fminf(bb.y + bb.w*0.5f, gy + gh*0.5f);
            float en  = (tlx < brx && tly < bry) ? 1.f : 0.f;
            float inter = fmaxf(brx - tlx, 0.f) * fmaxf(bry - tly, 0.f) * en;
            float uni = bb.z*bb.w + gw*gh - inter + 1e-16f;
            float iou = inter / uni;
            liou = 1.f - iou * iou;

            int mcls = g_gtcls[gi];
            int hw, W, HW; float st;
            anchor_map(a, hw, W, HW, st);
            const float* src = (a < 6400) ? out0 : (a < 8000) ? out1 : out2;
            const float* p = src + (size_t)b * 85 * HW + hw;
            #pragma unroll 4
            for (int c = 0; c < NC_; c++) {
                float x = __ldg(&p[(5 + c) * HW]);
                float t = (c == mcls) ? piou : 0.f;
                lcls += bce_logit(x, t);
            }
        }
    }

    #pragma unroll
    for (int off = 16; off; off >>= 1) {
        liou += __shfl_down_sync(0xffffffffu, liou, off);
        lobj += __shfl_down_sync(0xffffffffu, lobj, off);
        lcls += __shfl_down_sync(0xffffffffu, lcls, off);
        lfg  += __shfl_down_sync(0xffffffffu, lfg,  off);
    }
    __shared__ float s4[8][4];
    int wid = threadIdx.x >> 5, lane = threadIdx.x & 31;
    if (lane == 0) { s4[wid][0] = liou; s4[wid][1] = lobj; s4[wid][2] = lcls; s4[wid][3] = lfg; }
    __syncthreads();
    if (threadIdx.x == 0) {
        float a0 = 0.f, a1 = 0.f, a2 = 0.f, a3 = 0.f;
        for (int i = 0; i < 8; i++) { a0 += s4[i][0]; a1 += s4[i][1]; a2 += s4[i][2]; a3 += s4[i][3]; }
        if (a0 != 0.f) atomicAdd(&g_accb[b][0], (double)a0);
        if (a1 != 0.f) atomicAdd(&g_accb[b][1], (double)a1);
        if (a2 != 0.f) atomicAdd(&g_accb[b][2], (double)a2);
        if (a3 != 0.f) atomicAdd(&g_accb[b][3], (double)a3);
    }
}

// ---------------- K7: finalize ----------------
__global__ void k_final(float* __restrict__ out) {
    if (threadIdx.x == 0) {
        double si = 0.0, so = 0.0, sc = 0.0, nf = 0.0;
        for (int b = 0; b < B_; b++) {
            si += g_accb[b][0]; so += g_accb[b][1];
            sc += g_accb[b][2]; nf += g_accb[b][3];
        }
        if (nf < 1.0) nf = 1.0;
        out[0] = (float)((5.0 * si + so + sc) / nf);
    }
}

// ---------------- launch ----------------
extern "C" void kernel_launch(void* const* d_in, const int* in_sizes, int n_in,
                              void* d_out, int out_size) {
    const float* out0   = (const float*)d_in[0];
    const float* out1   = (const float*)d_in[1];
    const float* out2   = (const float*)d_in[2];
    const float* labels = (const float*)d_in[3];
    float* out = (float*)d_out;

    k_gt<<<(B_*G_ + 127) / 128, 128>>>(labels);
    {
        dim3 g((NA_ + 255) / 256, B_);
        k_decode<<<g, 256>>>(out0, out1, out2);
    }
    k_compact<<<B_, 256>>>();
    {
        dim3 g((NA_ + 255) / 256, B_);
        k_cost<<<g, 256>>>(out0, out1, out2);
    }
    k_topk<<<(B_*G_*32 + 127) / 128, 128>>>();
    {
        dim3 g((NA_ + 255) / 256, B_);
        k_resolve<<<g, 256>>>(out0, out1, out2);
    }
    k_final<<<1, 32>>>(out);
}